// round 9
// baseline (speedup 1.0000x reference)
#include <cuda_runtime.h>
#include <cuda_bf16.h>

// Embedding gather: out[i, :] = table[ids[i], :]
// ids: int32 [819200], table: f32 [1e6, 32] (~128 MB; touched ~72 MB, kept L2-resident),
// out: f32 [819200, 32]
//
//  - table loads: L2::evict_last policy + L1::no_allocate (zero L1 reuse)
//  - output stores: st.global.wt — write-through, no L2 allocation for write-once
//    output; keeps L2 dedicated to the table
//  - 4 independent row-gathers per thread (best-known structure)

#define NSEG 4

__device__ __forceinline__ float4 ldg_table(const float4* p, unsigned long long pol) {
    float4 v;
    asm volatile("ld.global.nc.L1::no_allocate.L2::cache_hint.v4.f32 {%0,%1,%2,%3}, [%4], %5;"
                 : "=f"(v.x), "=f"(v.y), "=f"(v.z), "=f"(v.w)
                 : "l"(p), "l"(pol));
    return v;
}

__device__ __forceinline__ void stg_wt(float4* p, float4 v) {
    asm volatile("st.global.wt.v4.f32 [%0], {%1,%2,%3,%4};"
                 :: "l"(p), "f"(v.x), "f"(v.y), "f"(v.z), "f"(v.w)
                 : "memory");
}

__global__ void __launch_bounds__(256)
embedding_gather_kernel(const int* __restrict__ ids,
                        const float4* __restrict__ table4,
                        float4* __restrict__ out4,
                        int seg) {
    int i = blockIdx.x * blockDim.x + threadIdx.x;
    if (i >= seg) return;

    unsigned long long pol;
    asm volatile("createpolicy.fractional.L2::evict_last.b64 %0, 1.0;" : "=l"(pol));

    int idx[NSEG];
    int id[NSEG];
#pragma unroll
    for (int s = 0; s < NSEG; s++) {
        idx[s] = i + s * seg;
        id[s]  = __ldg(&ids[idx[s] >> 3]);
    }

    float4 v[NSEG];
#pragma unroll
    for (int s = 0; s < NSEG; s++)
        v[s] = ldg_table(&table4[(size_t)(unsigned)id[s] * 8 + (idx[s] & 7)], pol);

#pragma unroll
    for (int s = 0; s < NSEG; s++)
        stg_wt(&out4[idx[s]], v[s]);
}

extern "C" void kernel_launch(void* const* d_in, const int* in_sizes, int n_in,
                              void* d_out, int out_size) {
    // Resolve inputs by element count (table: 32,000,000 f32; ids: 819,200).
    const int*    ids;
    const float4* table;
    int n_rows;
    if (in_sizes[0] > in_sizes[1]) {
        table = (const float4*)d_in[0];
        ids   = (const int*)d_in[1];
        n_rows = in_sizes[1];
    } else {
        ids   = (const int*)d_in[0];
        table = (const float4*)d_in[1];
        n_rows = in_sizes[0];
    }

    float4* out = (float4*)d_out;
    int n4 = n_rows * 8;          // total float4 elements (divisible by NSEG)
    int seg = n4 / NSEG;
    int threads = 256;
    int blocks = (seg + threads - 1) / threads;
    embedding_gather_kernel<<<blocks, threads>>>(ids, table, out, seg);
}

// round 10
// speedup vs baseline: 1.0621x; 1.0621x over previous
#include <cuda_runtime.h>
#include <cuda_bf16.h>

// Embedding gather: out[i, :] = table[ids[i], :]
// ids: int32 [819200], table: f32 [1e6, 32] (~128 MB; touched ~72 MB, kept L2-resident),
// out: f32 [819200, 32]
//
// Final configuration (best of 9 rounds, 33.54 us bench):
//  - table loads: L2::evict_last policy (table rows stay L2-resident across
//    graph replays) + L1::no_allocate (random 128B rows have ~0 L1 reuse)
//  - output stores: .cs streaming (evict-first; write-once output keeps its
//    L2 write-coalescing but doesn't displace the table)
//  - 4 independent row-gathers per thread (MLP sweet spot; 2/8/v8/wt all worse)

#define NSEG 4

__device__ __forceinline__ float4 ldg_table(const float4* p, unsigned long long pol) {
    float4 v;
    asm volatile("ld.global.nc.L1::no_allocate.L2::cache_hint.v4.f32 {%0,%1,%2,%3}, [%4], %5;"
                 : "=f"(v.x), "=f"(v.y), "=f"(v.z), "=f"(v.w)
                 : "l"(p), "l"(pol));
    return v;
}

__device__ __forceinline__ void stg_stream(float4* p, float4 v) {
    asm volatile("st.global.cs.v4.f32 [%0], {%1,%2,%3,%4};"
                 :: "l"(p), "f"(v.x), "f"(v.y), "f"(v.z), "f"(v.w)
                 : "memory");
}

__global__ void __launch_bounds__(256)
embedding_gather_kernel(const int* __restrict__ ids,
                        const float4* __restrict__ table4,
                        float4* __restrict__ out4,
                        int seg) {
    int i = blockIdx.x * blockDim.x + threadIdx.x;
    if (i >= seg) return;

    unsigned long long pol;
    asm volatile("createpolicy.fractional.L2::evict_last.b64 %0, 1.0;" : "=l"(pol));

    int idx[NSEG];
    int id[NSEG];
#pragma unroll
    for (int s = 0; s < NSEG; s++) {
        idx[s] = i + s * seg;
        id[s]  = __ldg(&ids[idx[s] >> 3]);
    }

    float4 v[NSEG];
#pragma unroll
    for (int s = 0; s < NSEG; s++)
        v[s] = ldg_table(&table4[(size_t)(unsigned)id[s] * 8 + (idx[s] & 7)], pol);

#pragma unroll
    for (int s = 0; s < NSEG; s++)
        stg_stream(&out4[idx[s]], v[s]);
}

extern "C" void kernel_launch(void* const* d_in, const int* in_sizes, int n_in,
                              void* d_out, int out_size) {
    // Resolve inputs by element count (table: 32,000,000 f32; ids: 819,200).
    const int*    ids;
    const float4* table;
    int n_rows;
    if (in_sizes[0] > in_sizes[1]) {
        table = (const float4*)d_in[0];
        ids   = (const int*)d_in[1];
        n_rows = in_sizes[1];
    } else {
        ids   = (const int*)d_in[0];
        table = (const float4*)d_in[1];
        n_rows = in_sizes[0];
    }

    float4* out = (float4*)d_out;
    int n4 = n_rows * 8;          // total float4 elements (divisible by NSEG)
    int seg = n4 / NSEG;
    int threads = 256;
    int blocks = (seg + threads - 1) / threads;
    embedding_gather_kernel<<<blocks, threads>>>(ids, table, out, seg);
}

// round 11
// speedup vs baseline: 1.0692x; 1.0067x over previous
#include <cuda_runtime.h>
#include <cuda_bf16.h>

// Embedding gather: out[i, :] = table[ids[i], :]
// ids: int32 [819200], table: f32 [1e6, 32] (~128 MB; touched ~72 MB, L2-resident),
// out: f32 [819200, 32]
//
//  - table loads: L2::evict_last policy + L1::no_allocate (zero L1 reuse)
//  - output stores: .cs streaming (evict-first; don't displace the table in L2)
//  - 4 independent row-gathers per thread (MLP sweet spot)
//  - warp-dedup id loads: 16 distinct ids per warp-iteration loaded once by
//    lanes 0..15, distributed via shfl (8x fewer id LDGs -> less L1tex pressure)

#define NSEG 4

__device__ __forceinline__ float4 ldg_table(const float4* p, unsigned long long pol) {
    float4 v;
    asm volatile("ld.global.nc.L1::no_allocate.L2::cache_hint.v4.f32 {%0,%1,%2,%3}, [%4], %5;"
                 : "=f"(v.x), "=f"(v.y), "=f"(v.z), "=f"(v.w)
                 : "l"(p), "l"(pol));
    return v;
}

__device__ __forceinline__ void stg_stream(float4* p, float4 v) {
    asm volatile("st.global.cs.v4.f32 [%0], {%1,%2,%3,%4};"
                 :: "l"(p), "f"(v.x), "f"(v.y), "f"(v.z), "f"(v.w)
                 : "memory");
}

__global__ void __launch_bounds__(256)
embedding_gather_kernel(const int* __restrict__ ids,
                        const float4* __restrict__ table4,
                        float4* __restrict__ out4,
                        int seg) {
    int warp_base = blockIdx.x * blockDim.x + (threadIdx.x & ~31);
    int lane = threadIdx.x & 31;
    int i = warp_base + lane;
    if (i >= seg) return;   // seg is a multiple of 32*... (1,638,400 = 256*6400), so
                            // whole warps are uniformly in/out; no divergence here.

    unsigned long long pol;
    asm volatile("createpolicy.fractional.L2::evict_last.b64 %0, 1.0;" : "=l"(pol));

    // Lanes 0..15 load the warp's 16 distinct ids:
    // lane l -> segment (l>>2), row offset (l&3) within that segment's 4-row span.
    int my_id = 0;
    if (lane < 16) {
        int s = lane >> 2;
        int r = ((warp_base + s * seg) >> 3) + (lane & 3);
        my_id = __ldg(&ids[r]);
    }

    int idx[NSEG];
    int id[NSEG];
#pragma unroll
    for (int s = 0; s < NSEG; s++) {
        idx[s] = i + s * seg;
        // source lane holding ids[(warp_base + s*seg)>>3 + (lane>>3)]
        id[s] = __shfl_sync(0xffffffffu, my_id, s * 4 + (lane >> 3));
    }

    float4 v[NSEG];
#pragma unroll
    for (int s = 0; s < NSEG; s++)
        v[s] = ldg_table(&table4[(size_t)(unsigned)id[s] * 8 + (idx[s] & 7)], pol);

#pragma unroll
    for (int s = 0; s < NSEG; s++)
        stg_stream(&out4[idx[s]], v[s]);
}

extern "C" void kernel_launch(void* const* d_in, const int* in_sizes, int n_in,
                              void* d_out, int out_size) {
    // Resolve inputs by element count (table: 32,000,000 f32; ids: 819,200).
    const int*    ids;
    const float4* table;
    int n_rows;
    if (in_sizes[0] > in_sizes[1]) {
        table = (const float4*)d_in[0];
        ids   = (const int*)d_in[1];
        n_rows = in_sizes[1];
    } else {
        ids   = (const int*)d_in[0];
        table = (const float4*)d_in[1];
        n_rows = in_sizes[0];
    }

    float4* out = (float4*)d_out;
    int n4 = n_rows * 8;          // total float4 elements (divisible by NSEG)
    int seg = n4 / NSEG;          // 1,638,400 = 256 * 6400 (whole warps/blocks)
    int threads = 256;
    int blocks = (seg + threads - 1) / threads;
    embedding_gather_kernel<<<blocks, threads>>>(ids, table, out, seg);
}